// round 15
// baseline (speedup 1.0000x reference)
#include <cuda_runtime.h>
#include <cuda_bf16.h>
#include <stdint.h>
#include <math.h>

#define BATCH 8
#define LSEQ 4096
#define DM 512
#define UK 45
#define UQ 45
#define RTOT 360
#define NSPL 8
#define PSCALE 0.044194173824159216f  // 1/sqrt(512)

__device__ float g_wkbq[DM];
__device__ float g_wvmean[DM];
__device__ float g_bvmean;
__device__ float g_c0[RTOT];
__device__ float g_meas[BATCH*LSEQ];
__device__ int   g_I[RTOT];
__device__ float g_S[RTOT*LSEQ];
__device__ __nv_bfloat16 g_Sh[RTOT*LSEQ];
__device__ __nv_bfloat16 g_Sl[RTOT*LSEQ];
__device__ float g_AVp[NSPL*RTOT*DM];
__device__ float g_P[4*DM*DM];      // M split-K partials (read-only after M gemm)
__device__ float g_P2[4*RTOT*DM];   // G / H2 / s1 split-K partials

__device__ __forceinline__ unsigned sptr(const void* p) {
    return (unsigned)__cvta_generic_to_shared(p);
}
__device__ __forceinline__ void cpa16(unsigned s, const void* g) {
    asm volatile("cp.async.cg.shared.global [%0], [%1], 16;" :: "r"(s), "l"(g));
}
__device__ __forceinline__ void cpa_commit() { asm volatile("cp.async.commit_group;" ::: "memory"); }
__device__ __forceinline__ void cpa_wait1()  { asm volatile("cp.async.wait_group 1;" ::: "memory"); }
__device__ __forceinline__ void cpa_wait0()  { asm volatile("cp.async.wait_group 0;" ::: "memory"); }

__device__ __forceinline__ void mma_bf16(float* c, const unsigned* a, const unsigned* b) {
    asm volatile("mma.sync.aligned.m16n8k16.row.col.f32.bf16.bf16.f32 "
        "{%0,%1,%2,%3}, {%4,%5,%6,%7}, {%8,%9}, {%0,%1,%2,%3};"
        : "+f"(c[0]), "+f"(c[1]), "+f"(c[2]), "+f"(c[3])
        : "r"(a[0]), "r"(a[1]), "r"(a[2]), "r"(a[3]), "r"(b[0]), "r"(b[1]));
}
__device__ __forceinline__ void ldm4(unsigned* r, unsigned a) {
    asm volatile("ldmatrix.sync.aligned.m8n8.x4.shared.b16 {%0,%1,%2,%3}, [%4];"
        : "=r"(r[0]), "=r"(r[1]), "=r"(r[2]), "=r"(r[3]) : "r"(a));
}
__device__ __forceinline__ void ldm2(unsigned* r, unsigned a) {
    asm volatile("ldmatrix.sync.aligned.m8n8.x2.shared.b16 {%0,%1}, [%2];"
        : "=r"(r[0]), "=r"(r[1]) : "r"(a));
}
__device__ __forceinline__ void ldm2t(unsigned* r, unsigned a) {
    asm volatile("ldmatrix.sync.aligned.m8n8.x2.trans.shared.b16 {%0,%1}, [%2];"
        : "=r"(r[0]), "=r"(r[1]) : "r"(a));
}
__device__ __forceinline__ void cvt_split(float x, __nv_bfloat16& h, __nv_bfloat16& l) {
    h = __float2bfloat16_rn(x);
    l = __float2bfloat16_rn(x - __bfloat162float(h));
}
__device__ __forceinline__ void store_split4(float4 v, __nv_bfloat16* dh, __nv_bfloat16* dl) {
    __nv_bfloat16 h0,l0,h1,l1,h2,l2,h3,l3;
    cvt_split(v.x,h0,l0); cvt_split(v.y,h1,l1);
    cvt_split(v.z,h2,l2); cvt_split(v.w,h3,l3);
    ((__nv_bfloat162*)dh)[0] = __nv_bfloat162{h0,h1};
    ((__nv_bfloat162*)dh)[1] = __nv_bfloat162{h2,h3};
    ((__nv_bfloat162*)dl)[0] = __nv_bfloat162{l0,l1};
    ((__nv_bfloat162*)dl)[1] = __nv_bfloat162{l2,l3};
}

// ---------------- prep ----------------
__global__ void prep_kernel(const float* __restrict__ WV, const float* __restrict__ bV,
                            const float* __restrict__ WK, const float* __restrict__ bQ) {
    int bid = blockIdx.x, tid = threadIdx.x;
    int w = tid >> 5, lane = tid & 31;
    if (bid < 32) {
        int row = bid*16 + w;
        float s = 0.f;
        #pragma unroll
        for (int j = 0; j < 16; j++) s += WV[row*DM + lane + 32*j];
        #pragma unroll
        for (int o = 16; o > 0; o >>= 1) s += __shfl_xor_sync(~0u, s, o);
        if (lane == 0) g_wvmean[row] = s * (1.0f/DM);
    } else if (bid < 64) {
        int row = (bid-32)*16 + w;
        float s = 0.f;
        #pragma unroll
        for (int j = 0; j < 16; j++) { int c = lane + 32*j; s += WK[row*DM + c]*bQ[c]; }
        #pragma unroll
        for (int o = 16; o > 0; o >>= 1) s += __shfl_xor_sync(~0u, s, o);
        if (lane == 0) g_wkbq[row] = s;
    } else {
        __shared__ float red[512];
        red[tid] = bV[tid]; __syncthreads();
        for (int st = 256; st > 0; st >>= 1) { if (tid < st) red[tid] += red[tid+st]; __syncthreads(); }
        if (tid == 0) g_bvmean = red[0] * (1.0f/DM);
    }
}

// ---------------- c0[r] = kbar_r . wkbq ----------------
__global__ void c0_kernel(const float* __restrict__ K, const int* __restrict__ kidx) {
    int r = blockIdx.x;
    int b = r / UK;
    const float* krow = K + ((long)b*LSEQ + kidx[r])*DM;
    int tid = threadIdx.x;  // 256
    float s = krow[tid]*g_wkbq[tid] + krow[tid+256]*g_wkbq[tid+256];
    int lane = tid & 31, w = tid >> 5;
    #pragma unroll
    for (int o = 16; o > 0; o >>= 1) s += __shfl_xor_sync(~0u, s, o);
    __shared__ float red[8];
    if (lane == 0) red[w] = s;
    __syncthreads();
    if (tid == 0) {
        float t = 0.f;
        #pragma unroll
        for (int i = 0; i < 8; i++) t += red[i];
        g_c0[r] = t;
    }
}

// ---------------- base rows ----------------
__global__ void base_kernel(const float* __restrict__ V, float* __restrict__ out) {
    int w = threadIdx.x >> 5, lane = threadIdx.x & 31;
    long row = (long)blockIdx.x*8 + w;
    const float4* v4 = (const float4*)(V + row*DM);
    const float4* w4 = (const float4*)g_wvmean;
    float s = 0.f;
    #pragma unroll
    for (int i = 0; i < 4; i++) {
        float4 a = v4[lane + 32*i], c = w4[lane + 32*i];
        s += a.x*c.x + a.y*c.y + a.z*c.z + a.w*c.w;
    }
    #pragma unroll
    for (int o = 16; o > 0; o >>= 1) s += __shfl_xor_sync(~0u, s, o);
    float r = s + g_bvmean;
    float4 ov = make_float4(r, r, r, r);
    float4* o4 = (float4*)(out + row*DM);
    #pragma unroll
    for (int i = 0; i < 4; i++) o4[lane + 32*i] = ov;
}

// ---------------- split-K(4) FFMA gemm ----------------
// SUMA: A = sum of NSPL partials (stride RTOT*DM). SUMB: B = sum of 4 partials (stride DM*DM).
template<int TRANSB, int GATHER, int SUMA, int SUMB>
__global__ void gemm512s(const float* __restrict__ A, const float* __restrict__ Bm,
                         float* __restrict__ P, long pstride,
                         int Mrows, const int* __restrict__ gidx) {
    const int BK = 32;
    __shared__ float As[2][64][36];
    __shared__ float BsT[TRANSB ? 2 : 1][TRANSB ? 64 : 1][TRANSB ? 36 : 1];
    __shared__ float BsN[TRANSB ? 1 : 2][TRANSB ? 1 : 32][TRANSB ? 1 : 68];
    int tid = threadIdx.x;
    int tx = tid & 15, ty = tid >> 4;
    int n0 = blockIdx.x * 64, m0 = blockIdx.y * 64;
    int kbase = blockIdx.z * 128;
    float acc[4][4] = {};
    auto sum4B = [&](long off) {
        float4 v = *(const float4*)(Bm + off);
        #pragma unroll
        for (int z = 1; z < 4; z++) {
            float4 p = *(const float4*)(Bm + (long)z*DM*DM + off);
            v.x += p.x; v.y += p.y; v.z += p.z; v.w += p.w;
        }
        return v;
    };
    auto load_tile = [&](int t, int buf) {
        int k0 = kbase + t * BK;
        #pragma unroll
        for (int j = 0; j < 2; j++) {
            int c = tid + 256*j, r = c >> 3, q = c & 7;
            int mm = m0 + r;
            if (mm < Mrows) {
                int arow;
                if (GATHER == 0)      arow = mm;
                else if (GATHER == 1) arow = (mm/UK)*LSEQ + gidx[mm];
                else                  arow = (mm/UK)*LSEQ + g_I[mm];
                if (SUMA) {
                    long off = (long)arow*DM + k0 + q*4;
                    float4 v = *(const float4*)(A + off);
                    #pragma unroll
                    for (int z = 1; z < NSPL; z++) {
                        float4 p = *(const float4*)(A + (long)z*RTOT*DM + off);
                        v.x += p.x; v.y += p.y; v.z += p.z; v.w += p.w;
                    }
                    *(float4*)&As[buf][r][q*4] = v;
                } else {
                    cpa16(sptr(&As[buf][r][q*4]), A + (long)arow*DM + k0 + q*4);
                }
            } else *(float4*)&As[buf][r][q*4] = make_float4(0.f,0.f,0.f,0.f);
        }
        if (TRANSB) {
            #pragma unroll
            for (int j = 0; j < 2; j++) {
                int c = tid + 256*j, r = c >> 3, q = c & 7;
                if (SUMB) *(float4*)&BsT[buf][r][q*4] = sum4B((long)(n0+r)*DM + k0 + q*4);
                else cpa16(sptr(&BsT[buf][r][q*4]), Bm + (long)(n0+r)*DM + k0 + q*4);
            }
        } else {
            #pragma unroll
            for (int j = 0; j < 2; j++) {
                int c = tid + 256*j, kk = c >> 4, q = c & 15;
                if (SUMB) *(float4*)&BsN[buf][kk][q*4] = sum4B((long)(k0+kk)*DM + n0 + q*4);
                else cpa16(sptr(&BsN[buf][kk][q*4]), Bm + (long)(k0+kk)*DM + n0 + q*4);
            }
        }
        cpa_commit();
    };
    load_tile(0, 0);
    for (int t = 0; t < 4; t++) {
        int buf = t & 1;
        if (t+1 < 4) { load_tile(t+1, buf^1); cpa_wait1(); } else cpa_wait0();
        __syncthreads();
        #pragma unroll
        for (int kk = 0; kk < BK; kk++) {
            float a[4], b[4];
            #pragma unroll
            for (int i = 0; i < 4; i++) a[i] = As[buf][ty + 16*i][kk];
            #pragma unroll
            for (int j = 0; j < 4; j++) b[j] = TRANSB ? BsT[buf][tx + 16*j][kk]
                                                      : BsN[buf][kk][tx + 16*j];
            #pragma unroll
            for (int i = 0; i < 4; i++)
                #pragma unroll
                for (int j = 0; j < 4; j++) acc[i][j] = fmaf(a[i], b[j], acc[i][j]);
        }
        __syncthreads();
    }
    float* Pz = P + (long)blockIdx.z * pstride;
    #pragma unroll
    for (int i = 0; i < 4; i++) {
        int mm = m0 + ty + 16*i;
        if (mm >= Mrows) continue;
        #pragma unroll
        for (int j = 0; j < 4; j++)
            Pz[(long)mm*DM + n0 + tx + 16*j] = acc[i][j];
    }
}

// ---------------- final reduce (4 partials from g_P2) + bias + scatter ----------------
__global__ void reduceP_final(const float* __restrict__ P,
                              const float* __restrict__ bias, float* __restrict__ C,
                              int nelem) {
    long e = ((long)blockIdx.x*256 + threadIdx.x) * 4;
    if (e >= nelem) return;
    float4 s = *(const float4*)(P + e);
    #pragma unroll
    for (int z = 1; z < 4; z++) {
        float4 p = *(const float4*)(P + (long)z*RTOT*DM + e);
        s.x += p.x; s.y += p.y; s.z += p.z; s.w += p.w;
    }
    int col = (int)(e & (DM-1));
    s.x += bias[col]; s.y += bias[col+1]; s.z += bias[col+2]; s.w += bias[col+3];
    long row = e >> 9;
    row = (long)(row/UK)*LSEQ + g_I[row];
    *(float4*)(C + row*DM + col) = s;
}

// ---------------- tallmma: bf16x3 MMA; Y = inline sum of 4 partials from g_P2 ----------------
#define XP 72
#define YP 72
template<int MODE>
__global__ void __launch_bounds__(256, 1) tallmma(const float* __restrict__ X) {
    extern __shared__ __align__(16) unsigned char smraw[];
    __nv_bfloat16* sXh = (__nv_bfloat16*)smraw;
    __nv_bfloat16* sXl = sXh + 128*XP;
    __nv_bfloat16* sYh = sXl + 128*XP;
    __nv_bfloat16* sYl = sYh + 48*YP;
    float* c0s = (float*)(sYl + 48*YP);

    int b = blockIdx.y, l0 = blockIdx.x * 128;
    int t = threadIdx.x, w = t >> 5, lane = t & 31;
    if (MODE == 0 && t < UK) c0s[t] = g_c0[b*UK + t];
    const float* Xb = X + ((long)b*LSEQ + l0)*DM;

    float acc[6][4];
    #pragma unroll
    for (int i = 0; i < 6; i++)
        #pragma unroll
        for (int j2 = 0; j2 < 4; j2++) acc[i][j2] = 0.f;

    int m0 = w*16;
    unsigned xh_b = sptr(sXh) + (((m0 + (lane&7) + ((lane>>3)&1)*8)*XP) + ((lane>>4)&1)*8)*2;
    unsigned xl_b = xh_b + 128*XP*2;
    unsigned yh_b = sptr(sYh) + (((lane&7))*YP + ((lane>>3)&1)*8)*2;
    unsigned yl_b = yh_b + 48*YP*2;

    int xr = t >> 1, xh2 = t & 1;

    float4 xreg[8], yreg[3];
    auto pfX = [&](int ch) {
        const float4* src = (const float4*)(Xb + (long)xr*DM + ch*64 + xh2*32);
        #pragma unroll
        for (int j = 0; j < 8; j++) xreg[j] = src[j];
    };
    auto pfY = [&](int ch) {
        #pragma unroll
        for (int j = 0; j < 3; j++) {
            int c = t + 256*j;
            int u = c >> 4, q4 = (c & 15)*4;
            float4 v = make_float4(0.f,0.f,0.f,0.f);
            if (u < UK) {
                long off = (long)(b*UK + u)*DM + ch*64 + q4;
                v = *(const float4*)(g_P2 + off);
                #pragma unroll
                for (int z = 1; z < 4; z++) {
                    float4 p = *(const float4*)(g_P2 + (long)z*RTOT*DM + off);
                    v.x += p.x; v.y += p.y; v.z += p.z; v.w += p.w;
                }
            } else if (MODE == 1 && u == UK) {
                v = *(const float4*)(g_wkbq + ch*64 + q4);
            }
            yreg[j] = v;
        }
    };

    pfX(0); pfY(0);
    for (int ch = 0; ch < 8; ch++) {
        __syncthreads();
        {
            __nv_bfloat16* dh = sXh + xr*XP + xh2*32;
            __nv_bfloat16* dl = sXl + xr*XP + xh2*32;
            #pragma unroll
            for (int j = 0; j < 8; j++) store_split4(xreg[j], dh + j*4, dl + j*4);
        }
        #pragma unroll
        for (int j = 0; j < 3; j++) {
            int c = t + 256*j;
            int u = c >> 4, q4 = (c & 15)*4;
            store_split4(yreg[j], sYh + u*YP + q4, sYl + u*YP + q4);
        }
        __syncthreads();
        if (ch < 7) { pfX(ch+1); pfY(ch+1); }
        #pragma unroll
        for (int k16 = 0; k16 < 64; k16 += 16) {
            unsigned ah[4], al[4];
            ldm4(ah, xh_b + k16*2);
            ldm4(al, xl_b + k16*2);
            #pragma unroll
            for (int nt = 0; nt < 6; nt++) {
                unsigned bh[2], bl[2];
                ldm2(bh, yh_b + (nt*8*YP + k16)*2);
                ldm2(bl, yl_b + (nt*8*YP + k16)*2);
                mma_bf16(acc[nt], ah, bh);
                mma_bf16(acc[nt], ah, bl);
                mma_bf16(acc[nt], al, bh);
            }
        }
    }
    int r = lane >> 2, jj = lane & 3;
    if (MODE == 0) {
        float mx0 = -INFINITY, mx1 = -INFINITY, s0 = 0.f, s1 = 0.f;
        #pragma unroll
        for (int nt = 0; nt < 6; nt++) {
            #pragma unroll
            for (int s = 0; s < 2; s++) {
                int col = nt*8 + 2*jj + s;
                if (col < UK) {
                    float cc = c0s[col];
                    float v0 = acc[nt][s] + cc;
                    float v1 = acc[nt][2+s] + cc;
                    mx0 = fmaxf(mx0, v0); s0 += v0;
                    mx1 = fmaxf(mx1, v1); s1 += v1;
                }
            }
        }
        #pragma unroll
        for (int o = 1; o <= 2; o <<= 1) {
            mx0 = fmaxf(mx0, __shfl_xor_sync(~0u, mx0, o));
            mx1 = fmaxf(mx1, __shfl_xor_sync(~0u, mx1, o));
            s0 += __shfl_xor_sync(~0u, s0, o);
            s1 += __shfl_xor_sync(~0u, s1, o);
        }
        if (jj == 0) {
            g_meas[b*LSEQ + l0 + m0 + r]     = mx0 - s0*(1.0f/UK);
            g_meas[b*LSEQ + l0 + m0 + r + 8] = mx1 - s1*(1.0f/UK);
        }
    } else {
        float ck0 = __shfl_sync(~0u, acc[5][1], (lane & ~3) | 2);
        float ck1 = __shfl_sync(~0u, acc[5][3], (lane & ~3) | 2);
        int l = l0 + m0 + r;
        #pragma unroll
        for (int nt = 0; nt < 6; nt++) {
            #pragma unroll
            for (int s = 0; s < 2; s++) {
                int col = nt*8 + 2*jj + s;
                if (col < UK) {
                    g_S[(long)(b*UK + col)*LSEQ + l]     = (acc[nt][s]   + ck0)*PSCALE;
                    g_S[(long)(b*UK + col)*LSEQ + l + 8] = (acc[nt][2+s] + ck1)*PSCALE;
                }
            }
        }
    }
}

// ---------------- topk radix select ----------------
__global__ void topk_kernel() {
    __shared__ unsigned um[LSEQ];
    __shared__ int hist[2048];
    __shared__ int eqbuf[256];
    __shared__ int s_rem, s_ngt, s_cntgt, s_cnteq;
    __shared__ unsigned s_prefmask, s_prefval;
    int b = blockIdx.x, tid = threadIdx.x;
    for (int i = tid; i < LSEQ; i += 512) {
        unsigned u = __float_as_uint(g_meas[b*LSEQ + i]);
        um[i] = (u & 0x80000000u) ? ~u : (u | 0x80000000u);
    }
    if (tid == 0) { s_rem = UQ; s_ngt = 0; s_prefmask = 0u; s_prefval = 0u; s_cntgt = 0; s_cnteq = 0; }
    __syncthreads();
    const int shifts[3] = {21, 10, 0};
    const unsigned bmask[3] = {0x7FFu, 0x7FFu, 0x3FFu};
    const int nbins[3] = {2048, 2048, 1024};
    for (int lev = 0; lev < 3; lev++) {
        for (int i = tid; i < nbins[lev]; i += 512) hist[i] = 0;
        __syncthreads();
        unsigned pm = s_prefmask, pv = s_prefval;
        for (int i = tid; i < LSEQ; i += 512) {
            unsigned k = um[i];
            if ((k & pm) == pv) atomicAdd(&hist[(k >> shifts[lev]) & bmask[lev]], 1);
        }
        __syncthreads();
        if (tid == 0) {
            int rem = s_rem, cum = 0, bsel = 0;
            for (int bin = nbins[lev]-1; bin >= 0; bin--) {
                cum += hist[bin];
                if (cum >= rem) { bsel = bin; break; }
            }
            s_ngt += cum - hist[bsel];
            s_rem = rem - (cum - hist[bsel]);
            s_prefmask |= bmask[lev] << shifts[lev];
            s_prefval  |= ((unsigned)bsel) << shifts[lev];
        }
        __syncthreads();
    }
    unsigned T = s_prefval;
    int n_gt = s_ngt;
    int need_eq = UQ - n_gt;
    for (int i = tid; i < LSEQ; i += 512) {
        unsigned k = um[i];
        if (k > T) { int p = atomicAdd(&s_cntgt, 1); g_I[b*UQ + p] = i; }
        else if (k == T) { int p = atomicAdd(&s_cnteq, 1); if (p < 256) eqbuf[p] = i; }
    }
    __syncthreads();
    if (tid == 0) {
        int ne = s_cnteq; if (ne > 256) ne = 256;
        for (int j = 0; j < need_eq; j++) {
            int bi = 0x7fffffff, bp = -1;
            for (int q = 0; q < ne; q++)
                if (eqbuf[q] < bi) { bi = eqbuf[q]; bp = q; }
            eqbuf[bp] = 0x7fffffff;
            g_I[b*UQ + n_gt + j] = bi;
        }
    }
}

// ---------------- softmax -> split bf16 ----------------
__global__ void softmax_kernel() {
    long roff = (long)blockIdx.x*LSEQ;
    const float* row = g_S + roff;
    int tid = threadIdx.x, lane = tid & 31, w = tid >> 5;
    __shared__ float red[8];
    float v[16];
    #pragma unroll
    for (int i = 0; i < 16; i++) v[i] = row[tid + 256*i];
    float m = -INFINITY;
    #pragma unroll
    for (int i = 0; i < 16; i++) m = fmaxf(m, v[i]);
    #pragma unroll
    for (int o = 16; o > 0; o >>= 1) m = fmaxf(m, __shfl_xor_sync(~0u, m, o));
    if (lane == 0) red[w] = m;
    __syncthreads();
    m = red[0];
    #pragma unroll
    for (int i = 1; i < 8; i++) m = fmaxf(m, red[i]);
    float e[16], s = 0.f;
    #pragma unroll
    for (int i = 0; i < 16; i++) { e[i] = expf(v[i] - m); s += e[i]; }
    #pragma unroll
    for (int o = 16; o > 0; o >>= 1) s += __shfl_xor_sync(~0u, s, o);
    __syncthreads();
    if (lane == 0) red[w] = s;
    __syncthreads();
    s = 0.f;
    #pragma unroll
    for (int i = 0; i < 8; i++) s += red[i];
    float inv = 1.0f / s;
    #pragma unroll
    for (int i = 0; i < 16; i++) {
        float p = e[i]*inv;
        __nv_bfloat16 h, l;
        cvt_split(p, h, l);
        g_Sh[roff + tid + 256*i] = h;
        g_Sl[roff + tid + 256*i] = l;
    }
}

// ---------------- avmma: 8 K-chunks of 512; register-prefetch ----------------
#define SP 72
#define VP 136
__global__ void __launch_bounds__(256, 1) avmma(const float* __restrict__ V) {
    extern __shared__ __align__(16) unsigned char smraw[];
    __nv_bfloat16* sSh = (__nv_bfloat16*)smraw;
    __nv_bfloat16* sSl = sSh + 64*SP;
    __nv_bfloat16* sVh = sSl + 64*SP;
    __nv_bfloat16* sVl = sVh + 64*VP;

    int nb = blockIdx.x, kc = blockIdx.y, b = blockIdx.z;
    int n0 = nb*128, kbase = kc*512;
    int t = threadIdx.x, w = t >> 5, lane = t & 31;
    int mt = w & 3, nh = w >> 2;

    for (int c = t; c < (64-UK)*16; c += 256) {
        int u = UK + (c >> 4), q4 = (c & 15)*4;
        *(uint2*)(sSh + u*SP + q4) = make_uint2(0u,0u);
        *(uint2*)(sSl + u*SP + q4) = make_uint2(0u,0u);
    }

    float acc[8][4];
    #pragma unroll
    for (int i = 0; i < 8; i++)
        #pragma unroll
        for (int j2 = 0; j2 < 4; j2++) acc[i][j2] = 0.f;

    unsigned ah_b = sptr(sSh) + (((mt*16 + (lane&7) + ((lane>>3)&1)*8)*SP) + ((lane>>4)&1)*8)*2;
    unsigned al_b = ah_b + 64*SP*2;
    unsigned vh_b = sptr(sVh) + (((lane&7) + ((lane>>3)&1)*8)*VP + nh*64)*2;
    unsigned vl_b = vh_b + 64*VP*2;

    int kr = t >> 2, qd = t & 3;

    float4 vreg[8];
    uint2 shreg[3], slreg[3];
    auto pf = [&](int ch) {
        int kb = kbase + ch*64;
        #pragma unroll
        for (int j = 0; j < 3; j++) {
            int c = t + 256*j;
            if (c < UK*16) {
                int u = c >> 4, q4 = (c & 15)*4;
                shreg[j] = *(const uint2*)(g_Sh + (long)(b*UK+u)*LSEQ + kb + q4);
                slreg[j] = *(const uint2*)(g_Sl + (long)(b*UK+u)*LSEQ + kb + q4);
            }
        }
        const float4* src = (const float4*)(V + ((long)b*LSEQ + kb + kr)*DM + n0 + qd*32);
        #pragma unroll
        for (int j = 0; j < 8; j++) vreg[j] = src[j];
    };

    pf(0);
    for (int ch = 0; ch < 8; ch++) {
        __syncthreads();
        #pragma unroll
        for (int j = 0; j < 3; j++) {
            int c = t + 256*j;
            if (c < UK*16) {
                int u = c >> 4, q4 = (c & 15)*4;
                *(uint2*)(sSh + u*SP + q4) = shreg[j];
                *(uint2*)(sSl + u*SP + q4) = slreg[j];
            }
        }
        {
            __nv_bfloat16* dh = sVh + kr*VP + qd*32;
            __nv_bfloat16* dl = sVl + kr*VP + qd*32;
            #pragma unroll
            for (int j = 0; j < 8; j++) store_split4(vreg[j], dh + j*4, dl + j*4);
        }
        __syncthreads();
        if (ch < 7) pf(ch+1);
        #pragma unroll
        for (int k16 = 0; k16 < 64; k16 += 16) {
            unsigned ah[4], al[4];
            ldm4(ah, ah_b + k16*2);
            ldm4(al, al_b + k16*2);
            #pragma unroll
            for (int nt = 0; nt < 8; nt++) {
                unsigned bh[2], bl[2];
                ldm2t(bh, vh_b + (k16*VP + nt*8)*2);
                ldm2t(bl, vl_b + (k16*VP + nt*8)*2);
                mma_bf16(acc[nt], ah, bh);
                mma_bf16(acc[nt], al, bh);
                mma_bf16(acc[nt], ah, bl);
            }
        }
    }
    int r = lane >> 2, jj = lane & 3;
    int u0 = mt*16 + r, u1 = u0 + 8;
    #pragma unroll
    for (int nt = 0; nt < 8; nt++) {
        int col = n0 + nh*64 + nt*8 + 2*jj;
        if (u0 < UK)
            *(float2*)&g_AVp[((long)kc*RTOT + b*UK + u0)*DM + col] = make_float2(acc[nt][0], acc[nt][1]);
        if (u1 < UK)
            *(float2*)&g_AVp[((long)kc*RTOT + b*UK + u1)*DM + col] = make_float2(acc[nt][2], acc[nt][3]);
    }
}

extern "C" void kernel_launch(void* const* d_in, const int* in_sizes, int n_in,
                              void* d_out, int out_size) {
    (void)in_sizes; (void)n_in; (void)out_size;
    const float* Q  = (const float*)d_in[0];
    const float* K  = (const float*)d_in[1];
    const float* V  = (const float*)d_in[2];
    const float* WQ = (const float*)d_in[3];
    const float* bQ = (const float*)d_in[4];
    const float* WK = (const float*)d_in[5];
    const float* WV = (const float*)d_in[7];
    const float* bV = (const float*)d_in[8];
    const int* kidx = (const int*)d_in[9];
    float* out = (float*)d_out;

    float *pAVp, *pP, *pP2;
    cudaGetSymbolAddress((void**)&pAVp, g_AVp);
    cudaGetSymbolAddress((void**)&pP,   g_P);
    cudaGetSymbolAddress((void**)&pP2,  g_P2);

    const int TSM = (128*XP + 128*XP + 48*YP + 48*YP)*2 + 256;
    const int ASM = (64*SP*2 + 64*VP*2)*2 + 64;
    cudaFuncSetAttribute(tallmma<0>, cudaFuncAttributeMaxDynamicSharedMemorySize, TSM);
    cudaFuncSetAttribute(tallmma<1>, cudaFuncAttributeMaxDynamicSharedMemorySize, TSM);
    cudaFuncSetAttribute(avmma, cudaFuncAttributeMaxDynamicSharedMemorySize, ASM);

    // --- side stream: prep -> c0, then base ---
    cudaStream_t side;
    cudaStreamCreateWithFlags(&side, cudaStreamNonBlocking);
    cudaEvent_t e0, eprep, ebase;
    cudaEventCreateWithFlags(&e0,    cudaEventDisableTiming);
    cudaEventCreateWithFlags(&eprep, cudaEventDisableTiming);
    cudaEventCreateWithFlags(&ebase, cudaEventDisableTiming);

    cudaEventRecord(e0, 0);
    cudaStreamWaitEvent(side, e0, 0);
    prep_kernel<<<65, 512, 0, side>>>(WV, bV, WK, bQ);
    c0_kernel<<<RTOT, 256, 0, side>>>(K, kidx);
    cudaEventRecord(eprep, side);
    base_kernel<<<BATCH*LSEQ/8, 256, 0, side>>>(V, out);
    cudaEventRecord(ebase, side);

    // main chain — M partials stay in g_P; G/H2/s1 partials in g_P2 (no aliasing)
    gemm512s<1,0,0,0><<<dim3(8,8,4), 256>>>(WQ, WK, pP, (long)DM*DM, 512, nullptr);    // M partials -> g_P
    gemm512s<1,1,0,1><<<dim3(8,6,4), 256>>>(K, pP, pP2, (long)RTOT*DM, RTOT, kidx);    // G partials -> g_P2 (B=sum M)
    cudaStreamWaitEvent(0, eprep, 0);                                                  // need c0
    tallmma<0><<<dim3(32, BATCH), 256, TSM>>>(Q);                                      // meas (sums G from g_P2)
    topk_kernel<<<BATCH, 512>>>();
    gemm512s<0,2,0,1><<<dim3(8,6,4), 256>>>(Q, pP, pP2, (long)RTOT*DM, RTOT, nullptr); // H2 partials -> g_P2 (B=sum M)
    tallmma<1><<<dim3(32, BATCH), 256, TSM>>>(K);                                      // logits (sums H2 from g_P2)
    softmax_kernel<<<RTOT, 256>>>();                                                   // -> Sh/Sl
    avmma<<<dim3(4,8,BATCH), 256, ASM>>>(V);                                           // attn@V partials (8-way)
    gemm512s<0,0,1,0><<<dim3(8,6,4), 256>>>(pAVp, WV, pP2, (long)RTOT*DM, RTOT, nullptr); // s1 partials -> g_P2 (SUMA=8)
    cudaStreamWaitEvent(0, ebase, 0);
    reduceP_final<<<180, 256>>>(pP2, bV, out, RTOT*DM);                                // + bias + scatter

    cudaEventDestroy(e0);
    cudaEventDestroy(eprep);
    cudaEventDestroy(ebase);
    cudaStreamDestroy(side);
}

// round 16
// speedup vs baseline: 1.0790x; 1.0790x over previous
#include <cuda_runtime.h>
#include <cuda_bf16.h>
#include <stdint.h>
#include <math.h>

#define BATCH 8
#define LSEQ 4096
#define DM 512
#define UK 45
#define UQ 45
#define RTOT 360
#define PSCALE 0.044194173824159216f  // 1/sqrt(512)

__device__ float g_M[DM*DM];
__device__ float g_wkbq[DM];
__device__ float g_wvmean[DM];
__device__ float g_bvmean;
__device__ float g_c0[RTOT];
__device__ float g_meas[BATCH*LSEQ];
__device__ int   g_I[RTOT];
__device__ float g_S[RTOT*LSEQ];
__device__ __nv_bfloat16 g_Sh[RTOT*LSEQ];
__device__ __nv_bfloat16 g_Sl[RTOT*LSEQ];
__device__ float g_AVp[4*RTOT*DM];
__device__ float g_P[4*DM*DM];

__device__ __forceinline__ unsigned sptr(const void* p) {
    return (unsigned)__cvta_generic_to_shared(p);
}
__device__ __forceinline__ void cpa16(unsigned s, const void* g) {
    asm volatile("cp.async.cg.shared.global [%0], [%1], 16;" :: "r"(s), "l"(g));
}
__device__ __forceinline__ void cpa_commit() { asm volatile("cp.async.commit_group;" ::: "memory"); }
__device__ __forceinline__ void cpa_wait1()  { asm volatile("cp.async.wait_group 1;" ::: "memory"); }
__device__ __forceinline__ void cpa_wait0()  { asm volatile("cp.async.wait_group 0;" ::: "memory"); }

__device__ __forceinline__ void mma_bf16(float* c, const unsigned* a, const unsigned* b) {
    asm volatile("mma.sync.aligned.m16n8k16.row.col.f32.bf16.bf16.f32 "
        "{%0,%1,%2,%3}, {%4,%5,%6,%7}, {%8,%9}, {%0,%1,%2,%3};"
        : "+f"(c[0]), "+f"(c[1]), "+f"(c[2]), "+f"(c[3])
        : "r"(a[0]), "r"(a[1]), "r"(a[2]), "r"(a[3]), "r"(b[0]), "r"(b[1]));
}
__device__ __forceinline__ void ldm4(unsigned* r, unsigned a) {
    asm volatile("ldmatrix.sync.aligned.m8n8.x4.shared.b16 {%0,%1,%2,%3}, [%4];"
        : "=r"(r[0]), "=r"(r[1]), "=r"(r[2]), "=r"(r[3]) : "r"(a));
}
__device__ __forceinline__ void ldm2(unsigned* r, unsigned a) {
    asm volatile("ldmatrix.sync.aligned.m8n8.x2.shared.b16 {%0,%1}, [%2];"
        : "=r"(r[0]), "=r"(r[1]) : "r"(a));
}
__device__ __forceinline__ void ldm2t(unsigned* r, unsigned a) {
    asm volatile("ldmatrix.sync.aligned.m8n8.x2.trans.shared.b16 {%0,%1}, [%2];"
        : "=r"(r[0]), "=r"(r[1]) : "r"(a));
}
__device__ __forceinline__ void cvt_split(float x, __nv_bfloat16& h, __nv_bfloat16& l) {
    h = __float2bfloat16_rn(x);
    l = __float2bfloat16_rn(x - __bfloat162float(h));
}
__device__ __forceinline__ void store_split4(float4 v, __nv_bfloat16* dh, __nv_bfloat16* dl) {
    __nv_bfloat16 h0,l0,h1,l1,h2,l2,h3,l3;
    cvt_split(v.x,h0,l0); cvt_split(v.y,h1,l1);
    cvt_split(v.z,h2,l2); cvt_split(v.w,h3,l3);
    ((__nv_bfloat162*)dh)[0] = __nv_bfloat162{h0,h1};
    ((__nv_bfloat162*)dh)[1] = __nv_bfloat162{h2,h3};
    ((__nv_bfloat162*)dl)[0] = __nv_bfloat162{l0,l1};
    ((__nv_bfloat162*)dl)[1] = __nv_bfloat162{l2,l3};
}

// ---------------- prep ----------------
__global__ void prep_kernel(const float* __restrict__ WV, const float* __restrict__ bV,
                            const float* __restrict__ WK, const float* __restrict__ bQ) {
    int bid = blockIdx.x, tid = threadIdx.x;
    int w = tid >> 5, lane = tid & 31;
    if (bid < 32) {
        int row = bid*16 + w;
        float s = 0.f;
        #pragma unroll
        for (int j = 0; j < 16; j++) s += WV[row*DM + lane + 32*j];
        #pragma unroll
        for (int o = 16; o > 0; o >>= 1) s += __shfl_xor_sync(~0u, s, o);
        if (lane == 0) g_wvmean[row] = s * (1.0f/DM);
    } else if (bid < 64) {
        int row = (bid-32)*16 + w;
        float s = 0.f;
        #pragma unroll
        for (int j = 0; j < 16; j++) { int c = lane + 32*j; s += WK[row*DM + c]*bQ[c]; }
        #pragma unroll
        for (int o = 16; o > 0; o >>= 1) s += __shfl_xor_sync(~0u, s, o);
        if (lane == 0) g_wkbq[row] = s;
    } else {
        __shared__ float red[512];
        red[tid] = bV[tid]; __syncthreads();
        for (int st = 256; st > 0; st >>= 1) { if (tid < st) red[tid] += red[tid+st]; __syncthreads(); }
        if (tid == 0) g_bvmean = red[0] * (1.0f/DM);
    }
}

// ---------------- base rows ----------------
__global__ void base_kernel(const float* __restrict__ V, float* __restrict__ out) {
    int w = threadIdx.x >> 5, lane = threadIdx.x & 31;
    long row = (long)blockIdx.x*8 + w;
    const float4* v4 = (const float4*)(V + row*DM);
    const float4* w4 = (const float4*)g_wvmean;
    float s = 0.f;
    #pragma unroll
    for (int i = 0; i < 4; i++) {
        float4 a = v4[lane + 32*i], c = w4[lane + 32*i];
        s += a.x*c.x + a.y*c.y + a.z*c.z + a.w*c.w;
    }
    #pragma unroll
    for (int o = 16; o > 0; o >>= 1) s += __shfl_xor_sync(~0u, s, o);
    float r = s + g_bvmean;
    float4 ov = make_float4(r, r, r, r);
    float4* o4 = (float4*)(out + row*DM);
    #pragma unroll
    for (int i = 0; i < 4; i++) o4[lane + 32*i] = ov;
}

// ---------------- split-K(4) FFMA gemm; SUMA: A = sum of 4 partials ----------------
template<int TRANSB, int GATHER, int SUMA>
__global__ void gemm512s(const float* __restrict__ A, const float* __restrict__ Bm,
                         float* __restrict__ P, long pstride,
                         int Mrows, const int* __restrict__ gidx) {
    const int BK = 32;
    __shared__ float As[2][64][36];
    __shared__ float BsT[TRANSB ? 2 : 1][TRANSB ? 64 : 1][TRANSB ? 36 : 1];
    __shared__ float BsN[TRANSB ? 1 : 2][TRANSB ? 1 : 32][TRANSB ? 1 : 68];
    int tid = threadIdx.x;
    int tx = tid & 15, ty = tid >> 4;
    int n0 = blockIdx.x * 64, m0 = blockIdx.y * 64;
    int kbase = blockIdx.z * 128;
    float acc[4][4] = {};
    auto load_tile = [&](int t, int buf) {
        int k0 = kbase + t * BK;
        #pragma unroll
        for (int j = 0; j < 2; j++) {
            int c = tid + 256*j, r = c >> 3, q = c & 7;
            int mm = m0 + r;
            if (mm < Mrows) {
                int arow;
                if (GATHER == 0)      arow = mm;
                else if (GATHER == 1) arow = (mm/UK)*LSEQ + gidx[mm];
                else                  arow = (mm/UK)*LSEQ + g_I[mm];
                if (SUMA) {
                    long off = (long)arow*DM + k0 + q*4;
                    float4 v = *(const float4*)(A + off);
                    #pragma unroll
                    for (int z = 1; z < 4; z++) {
                        float4 p = *(const float4*)(A + (long)z*RTOT*DM + off);
                        v.x += p.x; v.y += p.y; v.z += p.z; v.w += p.w;
                    }
                    *(float4*)&As[buf][r][q*4] = v;
                } else {
                    cpa16(sptr(&As[buf][r][q*4]), A + (long)arow*DM + k0 + q*4);
                }
            } else *(float4*)&As[buf][r][q*4] = make_float4(0.f,0.f,0.f,0.f);
        }
        if (TRANSB) {
            #pragma unroll
            for (int j = 0; j < 2; j++) {
                int c = tid + 256*j, r = c >> 3, q = c & 7;
                cpa16(sptr(&BsT[buf][r][q*4]), Bm + (long)(n0+r)*DM + k0 + q*4);
            }
        } else {
            #pragma unroll
            for (int j = 0; j < 2; j++) {
                int c = tid + 256*j, kk = c >> 4, q = c & 15;
                cpa16(sptr(&BsN[buf][kk][q*4]), Bm + (long)(k0+kk)*DM + n0 + q*4);
            }
        }
        cpa_commit();
    };
    load_tile(0, 0);
    for (int t = 0; t < 4; t++) {
        int buf = t & 1;
        if (t+1 < 4) { load_tile(t+1, buf^1); cpa_wait1(); } else cpa_wait0();
        __syncthreads();
        #pragma unroll
        for (int kk = 0; kk < BK; kk++) {
            float a[4], b[4];
            #pragma unroll
            for (int i = 0; i < 4; i++) a[i] = As[buf][ty + 16*i][kk];
            #pragma unroll
            for (int j = 0; j < 4; j++) b[j] = TRANSB ? BsT[buf][tx + 16*j][kk]
                                                      : BsN[buf][kk][tx + 16*j];
            #pragma unroll
            for (int i = 0; i < 4; i++)
                #pragma unroll
                for (int j = 0; j < 4; j++) acc[i][j] = fmaf(a[i], b[j], acc[i][j]);
        }
        __syncthreads();
    }
    float* Pz = P + (long)blockIdx.z * pstride;
    #pragma unroll
    for (int i = 0; i < 4; i++) {
        int mm = m0 + ty + 16*i;
        if (mm >= Mrows) continue;
        #pragma unroll
        for (int j = 0; j < 4; j++)
            Pz[(long)mm*DM + n0 + tx + 16*j] = acc[i][j];
    }
}

// ---------------- final reduce (4 partials) + bias + scatter ----------------
__global__ void reduceP_final(const float* __restrict__ P,
                              const float* __restrict__ bias, float* __restrict__ C,
                              int nelem) {
    long e = ((long)blockIdx.x*256 + threadIdx.x) * 4;
    if (e >= nelem) return;
    float4 s = *(const float4*)(P + e);
    #pragma unroll
    for (int z = 1; z < 4; z++) {
        float4 p = *(const float4*)(P + (long)z*RTOT*DM + e);
        s.x += p.x; s.y += p.y; s.z += p.z; s.w += p.w;
    }
    int col = (int)(e & (DM-1));
    s.x += bias[col]; s.y += bias[col+1]; s.z += bias[col+2]; s.w += bias[col+3];
    long row = e >> 9;
    row = (long)(row/UK)*LSEQ + g_I[row];
    *(float4*)(C + row*DM + col) = s;
}

// ---------------- reduce M partials (4) + c0 ----------------
__global__ void redM_c0_kernel(const float* __restrict__ K, const int* __restrict__ kidx) {
    int bx = blockIdx.x, tid = threadIdx.x;
    if (bx < 256) {
        long e = ((long)bx*256 + tid) * 4;
        float4 s = *(const float4*)(g_P + e);
        #pragma unroll
        for (int z = 1; z < 4; z++) {
            float4 p = *(const float4*)(g_P + (long)z*DM*DM + e);
            s.x += p.x; s.y += p.y; s.z += p.z; s.w += p.w;
        }
        *(float4*)(g_M + e) = s;
    } else {
        int r = bx - 256;
        int b = r / UK;
        const float* krow = K + ((long)b*LSEQ + kidx[r])*DM;
        float s = krow[tid]*g_wkbq[tid] + krow[tid+256]*g_wkbq[tid+256];
        int lane = tid & 31, w = tid >> 5;
        #pragma unroll
        for (int o = 16; o > 0; o >>= 1) s += __shfl_xor_sync(~0u, s, o);
        __shared__ float red[8];
        if (lane == 0) red[w] = s;
        __syncthreads();
        if (tid == 0) {
            float t = 0.f;
            #pragma unroll
            for (int i = 0; i < 8; i++) t += red[i];
            g_c0[r] = t;
        }
    }
}

// ---------------- tallmma: bf16x3 MMA; Y = inline sum of 4 split-K partials ----------------
#define XP 72
#define YP 72
template<int MODE>
__global__ void __launch_bounds__(256, 2) tallmma(const float* __restrict__ X) {
    extern __shared__ __align__(16) unsigned char smraw[];
    __nv_bfloat16* sXh = (__nv_bfloat16*)smraw;
    __nv_bfloat16* sXl = sXh + 128*XP;
    __nv_bfloat16* sYh = sXl + 128*XP;
    __nv_bfloat16* sYl = sYh + 48*YP;
    float* c0s = (float*)(sYl + 48*YP);

    int b = blockIdx.y, l0 = blockIdx.x * 128;
    int t = threadIdx.x, w = t >> 5, lane = t & 31;
    if (MODE == 0 && t < UK) c0s[t] = g_c0[b*UK + t];
    const float* Xb = X + ((long)b*LSEQ + l0)*DM;

    float acc[6][4];
    #pragma unroll
    for (int i = 0; i < 6; i++)
        #pragma unroll
        for (int j2 = 0; j2 < 4; j2++) acc[i][j2] = 0.f;

    int m0 = w*16;
    unsigned xh_b = sptr(sXh) + (((m0 + (lane&7) + ((lane>>3)&1)*8)*XP) + ((lane>>4)&1)*8)*2;
    unsigned xl_b = xh_b + 128*XP*2;
    unsigned yh_b = sptr(sYh) + (((lane&7))*YP + ((lane>>3)&1)*8)*2;
    unsigned yl_b = yh_b + 48*YP*2;

    int xr = t >> 1, xh2 = t & 1;

    float4 xreg[8], yreg[3];
    auto pfX = [&](int ch) {
        const float4* src = (const float4*)(Xb + (long)xr*DM + ch*64 + xh2*32);
        #pragma unroll
        for (int j = 0; j < 8; j++) xreg[j] = src[j];
    };
    auto pfY = [&](int ch) {
        #pragma unroll
        for (int j = 0; j < 3; j++) {
            int c = t + 256*j;
            int u = c >> 4, q4 = (c & 15)*4;
            float4 v = make_float4(0.f,0.f,0.f,0.f);
            if (u < UK) {
                long off = (long)(b*UK + u)*DM + ch*64 + q4;
                v = *(const float4*)(g_P + off);
                #pragma unroll
                for (int z = 1; z < 4; z++) {
                    float4 p = *(const float4*)(g_P + (long)z*RTOT*DM + off);
                    v.x += p.x; v.y += p.y; v.z += p.z; v.w += p.w;
                }
            } else if (MODE == 1 && u == UK) {
                v = *(const float4*)(g_wkbq + ch*64 + q4);
            }
            yreg[j] = v;
        }
    };

    pfX(0); pfY(0);
    for (int ch = 0; ch < 8; ch++) {
        __syncthreads();
        {
            __nv_bfloat16* dh = sXh + xr*XP + xh2*32;
            __nv_bfloat16* dl = sXl + xr*XP + xh2*32;
            #pragma unroll
            for (int j = 0; j < 8; j++) store_split4(xreg[j], dh + j*4, dl + j*4);
        }
        #pragma unroll
        for (int j = 0; j < 3; j++) {
            int c = t + 256*j;
            int u = c >> 4, q4 = (c & 15)*4;
            store_split4(yreg[j], sYh + u*YP + q4, sYl + u*YP + q4);
        }
        __syncthreads();
        if (ch < 7) { pfX(ch+1); pfY(ch+1); }
        #pragma unroll
        for (int k16 = 0; k16 < 64; k16 += 16) {
            unsigned ah[4], al[4];
            ldm4(ah, xh_b + k16*2);
            ldm4(al, xl_b + k16*2);
            #pragma unroll
            for (int nt = 0; nt < 6; nt++) {
                unsigned bh[2], bl[2];
                ldm2(bh, yh_b + (nt*8*YP + k16)*2);
                ldm2(bl, yl_b + (nt*8*YP + k16)*2);
                mma_bf16(acc[nt], ah, bh);
                mma_bf16(acc[nt], ah, bl);
                mma_bf16(acc[nt], al, bh);
            }
        }
    }
    int r = lane >> 2, jj = lane & 3;
    if (MODE == 0) {
        float mx0 = -INFINITY, mx1 = -INFINITY, s0 = 0.f, s1 = 0.f;
        #pragma unroll
        for (int nt = 0; nt < 6; nt++) {
            #pragma unroll
            for (int s = 0; s < 2; s++) {
                int col = nt*8 + 2*jj + s;
                if (col < UK) {
                    float cc = c0s[col];
                    float v0 = acc[nt][s] + cc;
                    float v1 = acc[nt][2+s] + cc;
                    mx0 = fmaxf(mx0, v0); s0 += v0;
                    mx1 = fmaxf(mx1, v1); s1 += v1;
                }
            }
        }
        #pragma unroll
        for (int o = 1; o <= 2; o <<= 1) {
            mx0 = fmaxf(mx0, __shfl_xor_sync(~0u, mx0, o));
            mx1 = fmaxf(mx1, __shfl_xor_sync(~0u, mx1, o));
            s0 += __shfl_xor_sync(~0u, s0, o);
            s1 += __shfl_xor_sync(~0u, s1, o);
        }
        if (jj == 0) {
            g_meas[b*LSEQ + l0 + m0 + r]     = mx0 - s0*(1.0f/UK);
            g_meas[b*LSEQ + l0 + m0 + r + 8] = mx1 - s1*(1.0f/UK);
        }
    } else {
        float ck0 = __shfl_sync(~0u, acc[5][1], (lane & ~3) | 2);
        float ck1 = __shfl_sync(~0u, acc[5][3], (lane & ~3) | 2);
        int l = l0 + m0 + r;
        #pragma unroll
        for (int nt = 0; nt < 6; nt++) {
            #pragma unroll
            for (int s = 0; s < 2; s++) {
                int col = nt*8 + 2*jj + s;
                if (col < UK) {
                    g_S[(long)(b*UK + col)*LSEQ + l]     = (acc[nt][s]   + ck0)*PSCALE;
                    g_S[(long)(b*UK + col)*LSEQ + l + 8] = (acc[nt][2+s] + ck1)*PSCALE;
                }
            }
        }
    }
}

// ---------------- topk radix select ----------------
__global__ void topk_kernel() {
    __shared__ unsigned um[LSEQ];
    __shared__ int hist[2048];
    __shared__ int eqbuf[256];
    __shared__ int s_rem, s_ngt, s_cntgt, s_cnteq;
    __shared__ unsigned s_prefmask, s_prefval;
    int b = blockIdx.x, tid = threadIdx.x;
    for (int i = tid; i < LSEQ; i += 512) {
        unsigned u = __float_as_uint(g_meas[b*LSEQ + i]);
        um[i] = (u & 0x80000000u) ? ~u : (u | 0x80000000u);
    }
    if (tid == 0) { s_rem = UQ; s_ngt = 0; s_prefmask = 0u; s_prefval = 0u; s_cntgt = 0; s_cnteq = 0; }
    __syncthreads();
    const int shifts[3] = {21, 10, 0};
    const unsigned bmask[3] = {0x7FFu, 0x7FFu, 0x3FFu};
    const int nbins[3] = {2048, 2048, 1024};
    for (int lev = 0; lev < 3; lev++) {
        for (int i = tid; i < nbins[lev]; i += 512) hist[i] = 0;
        __syncthreads();
        unsigned pm = s_prefmask, pv = s_prefval;
        for (int i = tid; i < LSEQ; i += 512) {
            unsigned k = um[i];
            if ((k & pm) == pv) atomicAdd(&hist[(k >> shifts[lev]) & bmask[lev]], 1);
        }
        __syncthreads();
        if (tid == 0) {
            int rem = s_rem, cum = 0, bsel = 0;
            for (int bin = nbins[lev]-1; bin >= 0; bin--) {
                cum += hist[bin];
                if (cum >= rem) { bsel = bin; break; }
            }
            s_ngt += cum - hist[bsel];
            s_rem = rem - (cum - hist[bsel]);
            s_prefmask |= bmask[lev] << shifts[lev];
            s_prefval  |= ((unsigned)bsel) << shifts[lev];
        }
        __syncthreads();
    }
    unsigned T = s_prefval;
    int n_gt = s_ngt;
    int need_eq = UQ - n_gt;
    for (int i = tid; i < LSEQ; i += 512) {
        unsigned k = um[i];
        if (k > T) { int p = atomicAdd(&s_cntgt, 1); g_I[b*UQ + p] = i; }
        else if (k == T) { int p = atomicAdd(&s_cnteq, 1); if (p < 256) eqbuf[p] = i; }
    }
    __syncthreads();
    if (tid == 0) {
        int ne = s_cnteq; if (ne > 256) ne = 256;
        for (int j = 0; j < need_eq; j++) {
            int bi = 0x7fffffff, bp = -1;
            for (int q = 0; q < ne; q++)
                if (eqbuf[q] < bi) { bi = eqbuf[q]; bp = q; }
            eqbuf[bp] = 0x7fffffff;
            g_I[b*UQ + n_gt + j] = bi;
        }
    }
}

// ---------------- softmax -> split bf16 ----------------
__global__ void softmax_kernel() {
    long roff = (long)blockIdx.x*LSEQ;
    const float* row = g_S + roff;
    int tid = threadIdx.x, lane = tid & 31, w = tid >> 5;
    __shared__ float red[8];
    float v[16];
    #pragma unroll
    for (int i = 0; i < 16; i++) v[i] = row[tid + 256*i];
    float m = -INFINITY;
    #pragma unroll
    for (int i = 0; i < 16; i++) m = fmaxf(m, v[i]);
    #pragma unroll
    for (int o = 16; o > 0; o >>= 1) m = fmaxf(m, __shfl_xor_sync(~0u, m, o));
    if (lane == 0) red[w] = m;
    __syncthreads();
    m = red[0];
    #pragma unroll
    for (int i = 1; i < 8; i++) m = fmaxf(m, red[i]);
    float e[16], s = 0.f;
    #pragma unroll
    for (int i = 0; i < 16; i++) { e[i] = expf(v[i] - m); s += e[i]; }
    #pragma unroll
    for (int o = 16; o > 0; o >>= 1) s += __shfl_xor_sync(~0u, s, o);
    __syncthreads();
    if (lane == 0) red[w] = s;
    __syncthreads();
    s = 0.f;
    #pragma unroll
    for (int i = 0; i < 8; i++) s += red[i];
    float inv = 1.0f / s;
    #pragma unroll
    for (int i = 0; i < 16; i++) {
        float p = e[i]*inv;
        __nv_bfloat16 h, l;
        cvt_split(p, h, l);
        g_Sh[roff + tid + 256*i] = h;
        g_Sl[roff + tid + 256*i] = l;
    }
}

// ---------------- avmma: 4 K-chunks of 1024; register-prefetch ----------------
#define SP 72
#define VP 136
__global__ void __launch_bounds__(256, 2) avmma(const float* __restrict__ V) {
    extern __shared__ __align__(16) unsigned char smraw[];
    __nv_bfloat16* sSh = (__nv_bfloat16*)smraw;
    __nv_bfloat16* sSl = sSh + 64*SP;
    __nv_bfloat16* sVh = sSl + 64*SP;
    __nv_bfloat16* sVl = sVh + 64*VP;

    int nb = blockIdx.x, kc = blockIdx.y, b = blockIdx.z;
    int n0 = nb*128, kbase = kc*1024;
    int t = threadIdx.x, w = t >> 5, lane = t & 31;
    int mt = w & 3, nh = w >> 2;

    for (int c = t; c < (64-UK)*16; c += 256) {
        int u = UK + (c >> 4), q4 = (c & 15)*4;
        *(uint2*)(sSh + u*SP + q4) = make_uint2(0u,0u);
        *(uint2*)(sSl + u*SP + q4) = make_uint2(0u,0u);
    }

    float acc[8][4];
    #pragma unroll
    for (int i = 0; i < 8; i++)
        #pragma unroll
        for (int j2 = 0; j2 < 4; j2++) acc[i][j2] = 0.f;

    unsigned ah_b = sptr(sSh) + (((mt*16 + (lane&7) + ((lane>>3)&1)*8)*SP) + ((lane>>4)&1)*8)*2;
    unsigned al_b = ah_b + 64*SP*2;
    unsigned vh_b = sptr(sVh) + (((lane&7) + ((lane>>3)&1)*8)*VP + nh*64)*2;
    unsigned vl_b = vh_b + 64*VP*2;

    int kr = t >> 2, qd = t & 3;

    float4 vreg[8];
    uint2 shreg[3], slreg[3];
    auto pf = [&](int ch) {
        int kb = kbase + ch*64;
        #pragma unroll
        for (int j = 0; j < 3; j++) {
            int c = t + 256*j;
            if (c < UK*16) {
                int u = c >> 4, q4 = (c & 15)*4;
                shreg[j] = *(const uint2*)(g_Sh + (long)(b*UK+u)*LSEQ + kb + q4);
                slreg[j] = *(const uint2*)(g_Sl + (long)(b*UK+u)*LSEQ + kb + q4);
            }
        }
        const float4* src = (const float4*)(V + ((long)b*LSEQ + kb + kr)*DM + n0 + qd*32);
        #pragma unroll
        for (int j = 0; j < 8; j++) vreg[j] = src[j];
    };

    pf(0);
    for (int ch = 0; ch < 16; ch++) {
        __syncthreads();
        #pragma unroll
        for (int j = 0; j < 3; j++) {
            int c = t + 256*j;
            if (c < UK*16) {
                int u = c >> 4, q4 = (c & 15)*4;
                *(uint2*)(sSh + u*SP + q4) = shreg[j];
                *(uint2*)(sSl + u*SP + q4) = slreg[j];
            }
        }
        {
            __nv_bfloat16* dh = sVh + kr*VP + qd*32;
            __nv_bfloat16* dl = sVl + kr*VP + qd*32;
            #pragma unroll
            for (int j = 0; j < 8; j++) store_split4(vreg[j], dh + j*4, dl + j*4);
        }
        __syncthreads();
        if (ch < 15) pf(ch+1);
        #pragma unroll
        for (int k16 = 0; k16 < 64; k16 += 16) {
            unsigned ah[4], al[4];
            ldm4(ah, ah_b + k16*2);
            ldm4(al, al_b + k16*2);
            #pragma unroll
            for (int nt = 0; nt < 8; nt++) {
                unsigned bh[2], bl[2];
                ldm2t(bh, vh_b + (k16*VP + nt*8)*2);
                ldm2t(bl, vl_b + (k16*VP + nt*8)*2);
                mma_bf16(acc[nt], ah, bh);
                mma_bf16(acc[nt], al, bh);
                mma_bf16(acc[nt], ah, bl);
            }
        }
    }
    int r = lane >> 2, jj = lane & 3;
    int u0 = mt*16 + r, u1 = u0 + 8;
    #pragma unroll
    for (int nt = 0; nt < 8; nt++) {
        int col = n0 + nh*64 + nt*8 + 2*jj;
        if (u0 < UK)
            *(float2*)&g_AVp[((long)kc*RTOT + b*UK + u0)*DM + col] = make_float2(acc[nt][0], acc[nt][1]);
        if (u1 < UK)
            *(float2*)&g_AVp[((long)kc*RTOT + b*UK + u1)*DM + col] = make_float2(acc[nt][2], acc[nt][3]);
    }
}

extern "C" void kernel_launch(void* const* d_in, const int* in_sizes, int n_in,
                              void* d_out, int out_size) {
    (void)in_sizes; (void)n_in; (void)out_size;
    const float* Q  = (const float*)d_in[0];
    const float* K  = (const float*)d_in[1];
    const float* V  = (const float*)d_in[2];
    const float* WQ = (const float*)d_in[3];
    const float* bQ = (const float*)d_in[4];
    const float* WK = (const float*)d_in[5];
    const float* WV = (const float*)d_in[7];
    const float* bV = (const float*)d_in[8];
    const int* kidx = (const int*)d_in[9];
    float* out = (float*)d_out;

    float *pM, *pAVp, *pP;
    cudaGetSymbolAddress((void**)&pM,   g_M);
    cudaGetSymbolAddress((void**)&pAVp, g_AVp);
    cudaGetSymbolAddress((void**)&pP,   g_P);

    const int TSM = (128*XP + 128*XP + 48*YP + 48*YP)*2 + 256;
    const int ASM = (64*SP*2 + 64*VP*2)*2 + 64;
    cudaFuncSetAttribute(tallmma<0>, cudaFuncAttributeMaxDynamicSharedMemorySize, TSM);
    cudaFuncSetAttribute(tallmma<1>, cudaFuncAttributeMaxDynamicSharedMemorySize, TSM);
    cudaFuncSetAttribute(avmma, cudaFuncAttributeMaxDynamicSharedMemorySize, ASM);

    // --- side stream: prep + base overlap the main chain ---
    cudaStream_t side;
    cudaStreamCreateWithFlags(&side, cudaStreamNonBlocking);
    cudaEvent_t e0, eprep, ebase;
    cudaEventCreateWithFlags(&e0,    cudaEventDisableTiming);
    cudaEventCreateWithFlags(&eprep, cudaEventDisableTiming);
    cudaEventCreateWithFlags(&ebase, cudaEventDisableTiming);

    cudaEventRecord(e0, 0);
    cudaStreamWaitEvent(side, e0, 0);
    prep_kernel<<<65, 512, 0, side>>>(WV, bV, WK, bQ);
    cudaEventRecord(eprep, side);
    base_kernel<<<BATCH*LSEQ/8, 256, 0, side>>>(V, out);
    cudaEventRecord(ebase, side);

    // main chain (split-K=4 gemms; Y-partials summed inline in tallmma)
    gemm512s<1,0,0><<<dim3(8,8,4), 256>>>(WQ, WK, pP, (long)DM*DM, 512, nullptr);  // M partials
    cudaStreamWaitEvent(0, eprep, 0);
    redM_c0_kernel<<<256 + RTOT, 256>>>(K, kidx);                                  // M, c0
    gemm512s<1,1,0><<<dim3(8,6,4), 256>>>(K, pM, pP, (long)RTOT*DM, RTOT, kidx);   // G partials
    tallmma<0><<<dim3(32, BATCH), 256, TSM>>>(Q);                                  // meas (sums G inline)
    topk_kernel<<<BATCH, 512>>>();
    gemm512s<0,2,0><<<dim3(8,6,4), 256>>>(Q, pM, pP, (long)RTOT*DM, RTOT, nullptr); // H2 partials
    tallmma<1><<<dim3(32, BATCH), 256, TSM>>>(K);                                  // logits (sums H2 inline)
    softmax_kernel<<<RTOT, 256>>>();                                               // -> Sh/Sl
    avmma<<<dim3(4,4,BATCH), 256, ASM>>>(V);                                       // attn@V partials
    gemm512s<0,0,1><<<dim3(8,6,4), 256>>>(pAVp, WV, pP, (long)RTOT*DM, RTOT, nullptr); // s1 (SUMA)
    cudaStreamWaitEvent(0, ebase, 0);
    reduceP_final<<<180, 256>>>(pP, bV, out, RTOT*DM);                             // + bias + scatter

    cudaEventDestroy(e0);
    cudaEventDestroy(eprep);
    cudaEventDestroy(ebase);
    cudaStreamDestroy(side);
}

// round 17
// speedup vs baseline: 1.0841x; 1.0047x over previous
#include <cuda_runtime.h>
#include <cuda_bf16.h>
#include <stdint.h>
#include <math.h>

#define BATCH 8
#define LSEQ 4096
#define DM 512
#define UK 45
#define UQ 45
#define RTOT 360
#define NSPL 8
#define PSCALE 0.044194173824159216f  // 1/sqrt(512)

__device__ float g_M[DM*DM];
__device__ float g_wkbq[DM];
__device__ float g_wvmean[DM];
__device__ float g_bvmean;
__device__ float g_c0[RTOT];
__device__ float g_meas[BATCH*LSEQ];
__device__ int   g_I[RTOT];
__device__ float g_S[RTOT*LSEQ];
__device__ __nv_bfloat16 g_Sh[RTOT*LSEQ];
__device__ __nv_bfloat16 g_Sl[RTOT*LSEQ];
__device__ float g_AVp[NSPL*RTOT*DM];
__device__ float g_P[4*DM*DM];

__device__ __forceinline__ unsigned sptr(const void* p) {
    return (unsigned)__cvta_generic_to_shared(p);
}
__device__ __forceinline__ void cpa16(unsigned s, const void* g) {
    asm volatile("cp.async.cg.shared.global [%0], [%1], 16;" :: "r"(s), "l"(g));
}
__device__ __forceinline__ void cpa_commit() { asm volatile("cp.async.commit_group;" ::: "memory"); }
__device__ __forceinline__ void cpa_wait1()  { asm volatile("cp.async.wait_group 1;" ::: "memory"); }
__device__ __forceinline__ void cpa_wait0()  { asm volatile("cp.async.wait_group 0;" ::: "memory"); }

__device__ __forceinline__ void mma_bf16(float* c, const unsigned* a, const unsigned* b) {
    asm volatile("mma.sync.aligned.m16n8k16.row.col.f32.bf16.bf16.f32 "
        "{%0,%1,%2,%3}, {%4,%5,%6,%7}, {%8,%9}, {%0,%1,%2,%3};"
        : "+f"(c[0]), "+f"(c[1]), "+f"(c[2]), "+f"(c[3])
        : "r"(a[0]), "r"(a[1]), "r"(a[2]), "r"(a[3]), "r"(b[0]), "r"(b[1]));
}
__device__ __forceinline__ void ldm4(unsigned* r, unsigned a) {
    asm volatile("ldmatrix.sync.aligned.m8n8.x4.shared.b16 {%0,%1,%2,%3}, [%4];"
        : "=r"(r[0]), "=r"(r[1]), "=r"(r[2]), "=r"(r[3]) : "r"(a));
}
__device__ __forceinline__ void ldm2(unsigned* r, unsigned a) {
    asm volatile("ldmatrix.sync.aligned.m8n8.x2.shared.b16 {%0,%1}, [%2];"
        : "=r"(r[0]), "=r"(r[1]) : "r"(a));
}
__device__ __forceinline__ void ldm2t(unsigned* r, unsigned a) {
    asm volatile("ldmatrix.sync.aligned.m8n8.x2.trans.shared.b16 {%0,%1}, [%2];"
        : "=r"(r[0]), "=r"(r[1]) : "r"(a));
}
__device__ __forceinline__ void cvt_split(float x, __nv_bfloat16& h, __nv_bfloat16& l) {
    h = __float2bfloat16_rn(x);
    l = __float2bfloat16_rn(x - __bfloat162float(h));
}
__device__ __forceinline__ void store_split4(float4 v, __nv_bfloat16* dh, __nv_bfloat16* dl) {
    __nv_bfloat16 h0,l0,h1,l1,h2,l2,h3,l3;
    cvt_split(v.x,h0,l0); cvt_split(v.y,h1,l1);
    cvt_split(v.z,h2,l2); cvt_split(v.w,h3,l3);
    ((__nv_bfloat162*)dh)[0] = __nv_bfloat162{h0,h1};
    ((__nv_bfloat162*)dh)[1] = __nv_bfloat162{h2,h3};
    ((__nv_bfloat162*)dl)[0] = __nv_bfloat162{l0,l1};
    ((__nv_bfloat162*)dl)[1] = __nv_bfloat162{l2,l3};
}

// ---------------- prep ----------------
__global__ void prep_kernel(const float* __restrict__ WV, const float* __restrict__ bV,
                            const float* __restrict__ WK, const float* __restrict__ bQ) {
    int bid = blockIdx.x, tid = threadIdx.x;
    int w = tid >> 5, lane = tid & 31;
    if (bid < 32) {
        int row = bid*16 + w;
        float s = 0.f;
        #pragma unroll
        for (int j = 0; j < 16; j++) s += WV[row*DM + lane + 32*j];
        #pragma unroll
        for (int o = 16; o > 0; o >>= 1) s += __shfl_xor_sync(~0u, s, o);
        if (lane == 0) g_wvmean[row] = s * (1.0f/DM);
    } else if (bid < 64) {
        int row = (bid-32)*16 + w;
        float s = 0.f;
        #pragma unroll
        for (int j = 0; j < 16; j++) { int c = lane + 32*j; s += WK[row*DM + c]*bQ[c]; }
        #pragma unroll
        for (int o = 16; o > 0; o >>= 1) s += __shfl_xor_sync(~0u, s, o);
        if (lane == 0) g_wkbq[row] = s;
    } else {
        __shared__ float red[512];
        red[tid] = bV[tid]; __syncthreads();
        for (int st = 256; st > 0; st >>= 1) { if (tid < st) red[tid] += red[tid+st]; __syncthreads(); }
        if (tid == 0) g_bvmean = red[0] * (1.0f/DM);
    }
}

// ---------------- base rows ----------------
__global__ void base_kernel(const float* __restrict__ V, float* __restrict__ out) {
    int w = threadIdx.x >> 5, lane = threadIdx.x & 31;
    long row = (long)blockIdx.x*8 + w;
    const float4* v4 = (const float4*)(V + row*DM);
    const float4* w4 = (const float4*)g_wvmean;
    float s = 0.f;
    #pragma unroll
    for (int i = 0; i < 4; i++) {
        float4 a = v4[lane + 32*i], c = w4[lane + 32*i];
        s += a.x*c.x + a.y*c.y + a.z*c.z + a.w*c.w;
    }
    #pragma unroll
    for (int o = 16; o > 0; o >>= 1) s += __shfl_xor_sync(~0u, s, o);
    float r = s + g_bvmean;
    float4 ov = make_float4(r, r, r, r);
    float4* o4 = (float4*)(out + row*DM);
    #pragma unroll
    for (int i = 0; i < 4; i++) o4[lane + 32*i] = ov;
}

// ---------------- split-K(4) FFMA gemm; SUMA: A = sum of NSPL partials ----------------
template<int TRANSB, int GATHER, int SUMA>
__global__ void gemm512s(const float* __restrict__ A, const float* __restrict__ Bm,
                         float* __restrict__ P, long pstride,
                         int Mrows, const int* __restrict__ gidx) {
    const int BK = 32;
    __shared__ float As[2][64][36];
    __shared__ float BsT[TRANSB ? 2 : 1][TRANSB ? 64 : 1][TRANSB ? 36 : 1];
    __shared__ float BsN[TRANSB ? 1 : 2][TRANSB ? 1 : 32][TRANSB ? 1 : 68];
    int tid = threadIdx.x;
    int tx = tid & 15, ty = tid >> 4;
    int n0 = blockIdx.x * 64, m0 = blockIdx.y * 64;
    int kbase = blockIdx.z * 128;
    float acc[4][4] = {};
    auto load_tile = [&](int t, int buf) {
        int k0 = kbase + t * BK;
        #pragma unroll
        for (int j = 0; j < 2; j++) {
            int c = tid + 256*j, r = c >> 3, q = c & 7;
            int mm = m0 + r;
            if (mm < Mrows) {
                int arow;
                if (GATHER == 0)      arow = mm;
                else if (GATHER == 1) arow = (mm/UK)*LSEQ + gidx[mm];
                else                  arow = (mm/UK)*LSEQ + g_I[mm];
                if (SUMA) {
                    long off = (long)arow*DM + k0 + q*4;
                    float4 v = *(const float4*)(A + off);
                    #pragma unroll
                    for (int z = 1; z < NSPL; z++) {
                        float4 p = *(const float4*)(A + (long)z*RTOT*DM + off);
                        v.x += p.x; v.y += p.y; v.z += p.z; v.w += p.w;
                    }
                    *(float4*)&As[buf][r][q*4] = v;
                } else {
                    cpa16(sptr(&As[buf][r][q*4]), A + (long)arow*DM + k0 + q*4);
                }
            } else *(float4*)&As[buf][r][q*4] = make_float4(0.f,0.f,0.f,0.f);
        }
        if (TRANSB) {
            #pragma unroll
            for (int j = 0; j < 2; j++) {
                int c = tid + 256*j, r = c >> 3, q = c & 7;
                cpa16(sptr(&BsT[buf][r][q*4]), Bm + (long)(n0+r)*DM + k0 + q*4);
            }
        } else {
            #pragma unroll
            for (int j = 0; j < 2; j++) {
                int c = tid + 256*j, kk = c >> 4, q = c & 15;
                cpa16(sptr(&BsN[buf][kk][q*4]), Bm + (long)(k0+kk)*DM + n0 + q*4);
            }
        }
        cpa_commit();
    };
    load_tile(0, 0);
    for (int t = 0; t < 4; t++) {
        int buf = t & 1;
        if (t+1 < 4) { load_tile(t+1, buf^1); cpa_wait1(); } else cpa_wait0();
        __syncthreads();
        #pragma unroll
        for (int kk = 0; kk < BK; kk++) {
            float a[4], b[4];
            #pragma unroll
            for (int i = 0; i < 4; i++) a[i] = As[buf][ty + 16*i][kk];
            #pragma unroll
            for (int j = 0; j < 4; j++) b[j] = TRANSB ? BsT[buf][tx + 16*j][kk]
                                                      : BsN[buf][kk][tx + 16*j];
            #pragma unroll
            for (int i = 0; i < 4; i++)
                #pragma unroll
                for (int j = 0; j < 4; j++) acc[i][j] = fmaf(a[i], b[j], acc[i][j]);
        }
        __syncthreads();
    }
    float* Pz = P + (long)blockIdx.z * pstride;
    #pragma unroll
    for (int i = 0; i < 4; i++) {
        int mm = m0 + ty + 16*i;
        if (mm >= Mrows) continue;
        #pragma unroll
        for (int j = 0; j < 4; j++)
            Pz[(long)mm*DM + n0 + tx + 16*j] = acc[i][j];
    }
}

// ---------------- final reduce (4 partials) + bias + scatter ----------------
__global__ void reduceP_final(const float* __restrict__ P,
                              const float* __restrict__ bias, float* __restrict__ C,
                              int nelem) {
    long e = ((long)blockIdx.x*256 + threadIdx.x) * 4;
    if (e >= nelem) return;
    float4 s = *(const float4*)(P + e);
    #pragma unroll
    for (int z = 1; z < 4; z++) {
        float4 p = *(const float4*)(P + (long)z*RTOT*DM + e);
        s.x += p.x; s.y += p.y; s.z += p.z; s.w += p.w;
    }
    int col = (int)(e & (DM-1));
    s.x += bias[col]; s.y += bias[col+1]; s.z += bias[col+2]; s.w += bias[col+3];
    long row = e >> 9;
    row = (long)(row/UK)*LSEQ + g_I[row];
    *(float4*)(C + row*DM + col) = s;
}

// ---------------- reduce M partials (4) + c0 ----------------
__global__ void redM_c0_kernel(const float* __restrict__ K, const int* __restrict__ kidx) {
    int bx = blockIdx.x, tid = threadIdx.x;
    if (bx < 256) {
        long e = ((long)bx*256 + tid) * 4;
        float4 s = *(const float4*)(g_P + e);
        #pragma unroll
        for (int z = 1; z < 4; z++) {
            float4 p = *(const float4*)(g_P + (long)z*DM*DM + e);
            s.x += p.x; s.y += p.y; s.z += p.z; s.w += p.w;
        }
        *(float4*)(g_M + e) = s;
    } else {
        int r = bx - 256;
        int b = r / UK;
        const float* krow = K + ((long)b*LSEQ + kidx[r])*DM;
        float s = krow[tid]*g_wkbq[tid] + krow[tid+256]*g_wkbq[tid+256];
        int lane = tid & 31, w = tid >> 5;
        #pragma unroll
        for (int o = 16; o > 0; o >>= 1) s += __shfl_xor_sync(~0u, s, o);
        __shared__ float red[8];
        if (lane == 0) red[w] = s;
        __syncthreads();
        if (tid == 0) {
            float t = 0.f;
            #pragma unroll
            for (int i = 0; i < 8; i++) t += red[i];
            g_c0[r] = t;
        }
    }
}

// ---------------- tallmma: bf16x3 MMA; Y = inline sum of 4 split-K partials ----------------
#define XP 72
#define YP 72
template<int MODE>
__global__ void __launch_bounds__(256, 2) tallmma(const float* __restrict__ X) {
    extern __shared__ __align__(16) unsigned char smraw[];
    __nv_bfloat16* sXh = (__nv_bfloat16*)smraw;
    __nv_bfloat16* sXl = sXh + 128*XP;
    __nv_bfloat16* sYh = sXl + 128*XP;
    __nv_bfloat16* sYl = sYh + 48*YP;
    float* c0s = (float*)(sYl + 48*YP);

    int b = blockIdx.y, l0 = blockIdx.x * 128;
    int t = threadIdx.x, w = t >> 5, lane = t & 31;
    if (MODE == 0 && t < UK) c0s[t] = g_c0[b*UK + t];
    const float* Xb = X + ((long)b*LSEQ + l0)*DM;

    float acc[6][4];
    #pragma unroll
    for (int i = 0; i < 6; i++)
        #pragma unroll
        for (int j2 = 0; j2 < 4; j2++) acc[i][j2] = 0.f;

    int m0 = w*16;
    unsigned xh_b = sptr(sXh) + (((m0 + (lane&7) + ((lane>>3)&1)*8)*XP) + ((lane>>4)&1)*8)*2;
    unsigned xl_b = xh_b + 128*XP*2;
    unsigned yh_b = sptr(sYh) + (((lane&7))*YP + ((lane>>3)&1)*8)*2;
    unsigned yl_b = yh_b + 48*YP*2;

    int xr = t >> 1, xh2 = t & 1;

    float4 xreg[8], yreg[3];
    auto pfX = [&](int ch) {
        const float4* src = (const float4*)(Xb + (long)xr*DM + ch*64 + xh2*32);
        #pragma unroll
        for (int j = 0; j < 8; j++) xreg[j] = src[j];
    };
    auto pfY = [&](int ch) {
        #pragma unroll
        for (int j = 0; j < 3; j++) {
            int c = t + 256*j;
            int u = c >> 4, q4 = (c & 15)*4;
            float4 v = make_float4(0.f,0.f,0.f,0.f);
            if (u < UK) {
                long off = (long)(b*UK + u)*DM + ch*64 + q4;
                v = *(const float4*)(g_P + off);
                #pragma unroll
                for (int z = 1; z < 4; z++) {
                    float4 p = *(const float4*)(g_P + (long)z*RTOT*DM + off);
                    v.x += p.x; v.y += p.y; v.z += p.z; v.w += p.w;
                }
            } else if (MODE == 1 && u == UK) {
                v = *(const float4*)(g_wkbq + ch*64 + q4);
            }
            yreg[j] = v;
        }
    };

    pfX(0); pfY(0);
    for (int ch = 0; ch < 8; ch++) {
        __syncthreads();
        {
            __nv_bfloat16* dh = sXh + xr*XP + xh2*32;
            __nv_bfloat16* dl = sXl + xr*XP + xh2*32;
            #pragma unroll
            for (int j = 0; j < 8; j++) store_split4(xreg[j], dh + j*4, dl + j*4);
        }
        #pragma unroll
        for (int j = 0; j < 3; j++) {
            int c = t + 256*j;
            int u = c >> 4, q4 = (c & 15)*4;
            store_split4(yreg[j], sYh + u*YP + q4, sYl + u*YP + q4);
        }
        __syncthreads();
        if (ch < 7) { pfX(ch+1); pfY(ch+1); }
        #pragma unroll
        for (int k16 = 0; k16 < 64; k16 += 16) {
            unsigned ah[4], al[4];
            ldm4(ah, xh_b + k16*2);
            ldm4(al, xl_b + k16*2);
            #pragma unroll
            for (int nt = 0; nt < 6; nt++) {
                unsigned bh[2], bl[2];
                ldm2(bh, yh_b + (nt*8*YP + k16)*2);
                ldm2(bl, yl_b + (nt*8*YP + k16)*2);
                mma_bf16(acc[nt], ah, bh);
                mma_bf16(acc[nt], ah, bl);
                mma_bf16(acc[nt], al, bh);
            }
        }
    }
    int r = lane >> 2, jj = lane & 3;
    if (MODE == 0) {
        float mx0 = -INFINITY, mx1 = -INFINITY, s0 = 0.f, s1 = 0.f;
        #pragma unroll
        for (int nt = 0; nt < 6; nt++) {
            #pragma unroll
            for (int s = 0; s < 2; s++) {
                int col = nt*8 + 2*jj + s;
                if (col < UK) {
                    float cc = c0s[col];
                    float v0 = acc[nt][s] + cc;
                    float v1 = acc[nt][2+s] + cc;
                    mx0 = fmaxf(mx0, v0); s0 += v0;
                    mx1 = fmaxf(mx1, v1); s1 += v1;
                }
            }
        }
        #pragma unroll
        for (int o = 1; o <= 2; o <<= 1) {
            mx0 = fmaxf(mx0, __shfl_xor_sync(~0u, mx0, o));
            mx1 = fmaxf(mx1, __shfl_xor_sync(~0u, mx1, o));
            s0 += __shfl_xor_sync(~0u, s0, o);
            s1 += __shfl_xor_sync(~0u, s1, o);
        }
        if (jj == 0) {
            g_meas[b*LSEQ + l0 + m0 + r]     = mx0 - s0*(1.0f/UK);
            g_meas[b*LSEQ + l0 + m0 + r + 8] = mx1 - s1*(1.0f/UK);
        }
    } else {
        float ck0 = __shfl_sync(~0u, acc[5][1], (lane & ~3) | 2);
        float ck1 = __shfl_sync(~0u, acc[5][3], (lane & ~3) | 2);
        int l = l0 + m0 + r;
        #pragma unroll
        for (int nt = 0; nt < 6; nt++) {
            #pragma unroll
            for (int s = 0; s < 2; s++) {
                int col = nt*8 + 2*jj + s;
                if (col < UK) {
                    g_S[(long)(b*UK + col)*LSEQ + l]     = (acc[nt][s]   + ck0)*PSCALE;
                    g_S[(long)(b*UK + col)*LSEQ + l + 8] = (acc[nt][2+s] + ck1)*PSCALE;
                }
            }
        }
    }
}

// ---------------- topk radix select ----------------
__global__ void topk_kernel() {
    __shared__ unsigned um[LSEQ];
    __shared__ int hist[2048];
    __shared__ int eqbuf[256];
    __shared__ int s_rem, s_ngt, s_cntgt, s_cnteq;
    __shared__ unsigned s_prefmask, s_prefval;
    int b = blockIdx.x, tid = threadIdx.x;
    for (int i = tid; i < LSEQ; i += 512) {
        unsigned u = __float_as_uint(g_meas[b*LSEQ + i]);
        um[i] = (u & 0x80000000u) ? ~u : (u | 0x80000000u);
    }
    if (tid == 0) { s_rem = UQ; s_ngt = 0; s_prefmask = 0u; s_prefval = 0u; s_cntgt = 0; s_cnteq = 0; }
    __syncthreads();
    const int shifts[3] = {21, 10, 0};
    const unsigned bmask[3] = {0x7FFu, 0x7FFu, 0x3FFu};
    const int nbins[3] = {2048, 2048, 1024};
    for (int lev = 0; lev < 3; lev++) {
        for (int i = tid; i < nbins[lev]; i += 512) hist[i] = 0;
        __syncthreads();
        unsigned pm = s_prefmask, pv = s_prefval;
        for (int i = tid; i < LSEQ; i += 512) {
            unsigned k = um[i];
            if ((k & pm) == pv) atomicAdd(&hist[(k >> shifts[lev]) & bmask[lev]], 1);
        }
        __syncthreads();
        if (tid == 0) {
            int rem = s_rem, cum = 0, bsel = 0;
            for (int bin = nbins[lev]-1; bin >= 0; bin--) {
                cum += hist[bin];
                if (cum >= rem) { bsel = bin; break; }
            }
            s_ngt += cum - hist[bsel];
            s_rem = rem - (cum - hist[bsel]);
            s_prefmask |= bmask[lev] << shifts[lev];
            s_prefval  |= ((unsigned)bsel) << shifts[lev];
        }
        __syncthreads();
    }
    unsigned T = s_prefval;
    int n_gt = s_ngt;
    int need_eq = UQ - n_gt;
    for (int i = tid; i < LSEQ; i += 512) {
        unsigned k = um[i];
        if (k > T) { int p = atomicAdd(&s_cntgt, 1); g_I[b*UQ + p] = i; }
        else if (k == T) { int p = atomicAdd(&s_cnteq, 1); if (p < 256) eqbuf[p] = i; }
    }
    __syncthreads();
    if (tid == 0) {
        int ne = s_cnteq; if (ne > 256) ne = 256;
        for (int j = 0; j < need_eq; j++) {
            int bi = 0x7fffffff, bp = -1;
            for (int q = 0; q < ne; q++)
                if (eqbuf[q] < bi) { bi = eqbuf[q]; bp = q; }
            eqbuf[bp] = 0x7fffffff;
            g_I[b*UQ + n_gt + j] = bi;
        }
    }
}

// ---------------- softmax -> split bf16 ----------------
__global__ void softmax_kernel() {
    long roff = (long)blockIdx.x*LSEQ;
    const float* row = g_S + roff;
    int tid = threadIdx.x, lane = tid & 31, w = tid >> 5;
    __shared__ float red[8];
    float v[16];
    #pragma unroll
    for (int i = 0; i < 16; i++) v[i] = row[tid + 256*i];
    float m = -INFINITY;
    #pragma unroll
    for (int i = 0; i < 16; i++) m = fmaxf(m, v[i]);
    #pragma unroll
    for (int o = 16; o > 0; o >>= 1) m = fmaxf(m, __shfl_xor_sync(~0u, m, o));
    if (lane == 0) red[w] = m;
    __syncthreads();
    m = red[0];
    #pragma unroll
    for (int i = 1; i < 8; i++) m = fmaxf(m, red[i]);
    float e[16], s = 0.f;
    #pragma unroll
    for (int i = 0; i < 16; i++) { e[i] = expf(v[i] - m); s += e[i]; }
    #pragma unroll
    for (int o = 16; o > 0; o >>= 1) s += __shfl_xor_sync(~0u, s, o);
    __syncthreads();
    if (lane == 0) red[w] = s;
    __syncthreads();
    s = 0.f;
    #pragma unroll
    for (int i = 0; i < 8; i++) s += red[i];
    float inv = 1.0f / s;
    #pragma unroll
    for (int i = 0; i < 16; i++) {
        float p = e[i]*inv;
        __nv_bfloat16 h, l;
        cvt_split(p, h, l);
        g_Sh[roff + tid + 256*i] = h;
        g_Sl[roff + tid + 256*i] = l;
    }
}

// ---------------- avmma: 8 K-chunks of 512; register-prefetch ----------------
#define SP 72
#define VP 136
__global__ void __launch_bounds__(256, 2) avmma(const float* __restrict__ V) {
    extern __shared__ __align__(16) unsigned char smraw[];
    __nv_bfloat16* sSh = (__nv_bfloat16*)smraw;
    __nv_bfloat16* sSl = sSh + 64*SP;
    __nv_bfloat16* sVh = sSl + 64*SP;
    __nv_bfloat16* sVl = sVh + 64*VP;

    int nb = blockIdx.x, kc = blockIdx.y, b = blockIdx.z;
    int n0 = nb*128, kbase = kc*512;
    int t = threadIdx.x, w = t >> 5, lane = t & 31;
    int mt = w & 3, nh = w >> 2;

    for (int c = t; c < (64-UK)*16; c += 256) {
        int u = UK + (c >> 4), q4 = (c & 15)*4;
        *(uint2*)(sSh + u*SP + q4) = make_uint2(0u,0u);
        *(uint2*)(sSl + u*SP + q4) = make_uint2(0u,0u);
    }

    float acc[8][4];
    #pragma unroll
    for (int i = 0; i < 8; i++)
        #pragma unroll
        for (int j2 = 0; j2 < 4; j2++) acc[i][j2] = 0.f;

    unsigned ah_b = sptr(sSh) + (((mt*16 + (lane&7) + ((lane>>3)&1)*8)*SP) + ((lane>>4)&1)*8)*2;
    unsigned al_b = ah_b + 64*SP*2;
    unsigned vh_b = sptr(sVh) + (((lane&7) + ((lane>>3)&1)*8)*VP + nh*64)*2;
    unsigned vl_b = vh_b + 64*VP*2;

    int kr = t >> 2, qd = t & 3;

    float4 vreg[8];
    uint2 shreg[3], slreg[3];
    auto pf = [&](int ch) {
        int kb = kbase + ch*64;
        #pragma unroll
        for (int j = 0; j < 3; j++) {
            int c = t + 256*j;
            if (c < UK*16) {
                int u = c >> 4, q4 = (c & 15)*4;
                shreg[j] = *(const uint2*)(g_Sh + (long)(b*UK+u)*LSEQ + kb + q4);
                slreg[j] = *(const uint2*)(g_Sl + (long)(b*UK+u)*LSEQ + kb + q4);
            }
        }
        const float4* src = (const float4*)(V + ((long)b*LSEQ + kb + kr)*DM + n0 + qd*32);
        #pragma unroll
        for (int j = 0; j < 8; j++) vreg[j] = src[j];
    };

    pf(0);
    for (int ch = 0; ch < 8; ch++) {
        __syncthreads();
        #pragma unroll
        for (int j = 0; j < 3; j++) {
            int c = t + 256*j;
            if (c < UK*16) {
                int u = c >> 4, q4 = (c & 15)*4;
                *(uint2*)(sSh + u*SP + q4) = shreg[j];
                *(uint2*)(sSl + u*SP + q4) = slreg[j];
            }
        }
        {
            __nv_bfloat16* dh = sVh + kr*VP + qd*32;
            __nv_bfloat16* dl = sVl + kr*VP + qd*32;
            #pragma unroll
            for (int j = 0; j < 8; j++) store_split4(vreg[j], dh + j*4, dl + j*4);
        }
        __syncthreads();
        if (ch < 7) pf(ch+1);
        #pragma unroll
        for (int k16 = 0; k16 < 64; k16 += 16) {
            unsigned ah[4], al[4];
            ldm4(ah, ah_b + k16*2);
            ldm4(al, al_b + k16*2);
            #pragma unroll
            for (int nt = 0; nt < 8; nt++) {
                unsigned bh[2], bl[2];
                ldm2t(bh, vh_b + (k16*VP + nt*8)*2);
                ldm2t(bl, vl_b + (k16*VP + nt*8)*2);
                mma_bf16(acc[nt], ah, bh);
                mma_bf16(acc[nt], al, bh);
                mma_bf16(acc[nt], ah, bl);
            }
        }
    }
    int r = lane >> 2, jj = lane & 3;
    int u0 = mt*16 + r, u1 = u0 + 8;
    #pragma unroll
    for (int nt = 0; nt < 8; nt++) {
        int col = n0 + nh*64 + nt*8 + 2*jj;
        if (u0 < UK)
            *(float2*)&g_AVp[((long)kc*RTOT + b*UK + u0)*DM + col] = make_float2(acc[nt][0], acc[nt][1]);
        if (u1 < UK)
            *(float2*)&g_AVp[((long)kc*RTOT + b*UK + u1)*DM + col] = make_float2(acc[nt][2], acc[nt][3]);
    }
}

extern "C" void kernel_launch(void* const* d_in, const int* in_sizes, int n_in,
                              void* d_out, int out_size) {
    (void)in_sizes; (void)n_in; (void)out_size;
    const float* Q  = (const float*)d_in[0];
    const float* K  = (const float*)d_in[1];
    const float* V  = (const float*)d_in[2];
    const float* WQ = (const float*)d_in[3];
    const float* bQ = (const float*)d_in[4];
    const float* WK = (const float*)d_in[5];
    const float* WV = (const float*)d_in[7];
    const float* bV = (const float*)d_in[8];
    const int* kidx = (const int*)d_in[9];
    float* out = (float*)d_out;

    float *pM, *pAVp, *pP;
    cudaGetSymbolAddress((void**)&pM,   g_M);
    cudaGetSymbolAddress((void**)&pAVp, g_AVp);
    cudaGetSymbolAddress((void**)&pP,   g_P);

    const int TSM = (128*XP + 128*XP + 48*YP + 48*YP)*2 + 256;
    const int ASM = (64*SP*2 + 64*VP*2)*2 + 64;
    cudaFuncSetAttribute(tallmma<0>, cudaFuncAttributeMaxDynamicSharedMemorySize, TSM);
    cudaFuncSetAttribute(tallmma<1>, cudaFuncAttributeMaxDynamicSharedMemorySize, TSM);
    cudaFuncSetAttribute(avmma, cudaFuncAttributeMaxDynamicSharedMemorySize, ASM);

    // --- side stream: prep + base overlap the main chain ---
    cudaStream_t side;
    cudaStreamCreateWithFlags(&side, cudaStreamNonBlocking);
    cudaEvent_t e0, eprep, ebase;
    cudaEventCreateWithFlags(&e0,    cudaEventDisableTiming);
    cudaEventCreateWithFlags(&eprep, cudaEventDisableTiming);
    cudaEventCreateWithFlags(&ebase, cudaEventDisableTiming);

    cudaEventRecord(e0, 0);
    cudaStreamWaitEvent(side, e0, 0);
    prep_kernel<<<65, 512, 0, side>>>(WV, bV, WK, bQ);
    cudaEventRecord(eprep, side);
    base_kernel<<<BATCH*LSEQ/8, 256, 0, side>>>(V, out);
    cudaEventRecord(ebase, side);

    // main chain
    gemm512s<1,0,0><<<dim3(8,8,4), 256>>>(WQ, WK, pP, (long)DM*DM, 512, nullptr);  // M partials
    cudaStreamWaitEvent(0, eprep, 0);
    redM_c0_kernel<<<256 + RTOT, 256>>>(K, kidx);                                  // M, c0
    gemm512s<1,1,0><<<dim3(8,6,4), 256>>>(K, pM, pP, (long)RTOT*DM, RTOT, kidx);   // G partials
    tallmma<0><<<dim3(32, BATCH), 256, TSM>>>(Q);                                  // meas (sums G inline)
    topk_kernel<<<BATCH, 512>>>();
    gemm512s<0,2,0><<<dim3(8,6,4), 256>>>(Q, pM, pP, (long)RTOT*DM, RTOT, nullptr); // H2 partials
    tallmma<1><<<dim3(32, BATCH), 256, TSM>>>(K);                                  // logits (sums H2 inline)
    softmax_kernel<<<RTOT, 256>>>();                                               // -> Sh/Sl
    avmma<<<dim3(4,8,BATCH), 256, ASM>>>(V);                                       // attn@V partials (8-way)
    gemm512s<0,0,1><<<dim3(8,6,4), 256>>>(pAVp, WV, pP, (long)RTOT*DM, RTOT, nullptr); // s1 (SUMA=8)
    cudaStreamWaitEvent(0, ebase, 0);
    reduceP_final<<<180, 256>>>(pP, bV, out, RTOT*DM);                             // + bias + scatter

    cudaEventDestroy(e0);
    cudaEventDestroy(eprep);
    cudaEventDestroy(ebase);
    cudaStreamDestroy(side);
}